// round 7
// baseline (speedup 1.0000x reference)
#include <cuda_runtime.h>

// Actor_Critic fused — Round 6: fp32 FFMA2, M=64 rows/block, 512 threads (16 warps),
// 1 row/thread, 16-col warps on big GEMMs (halves LDS traffic), occ 25%.

#define B_TOTAL 32768
#define M 64
#define STRIDE 772           // 3*256+4 floats; lane stride 772 % 32 = 4 -> LDS.128 conflict-free per phase
#define NTHREADS 512
#define S0 0
#define S1 256
#define S2 512

#define OFF_VAL 0
#define OFF_POL (B_TOTAL)
#define OFF_HX  (B_TOTAL * 4)
#define OFF_CX  (B_TOTAL * 4 + B_TOTAL * 256)

typedef unsigned long long u64;

// column-major scratch: g_val[c * B_TOTAL + row]
__device__ float g_val[(size_t)256 * B_TOTAL];

struct P {
    const float *img, *hx0, *cx0, *query, *emb;
    const float *w_ta, *b_ta, *w_ih, *w_hh, *b_ih, *b_hh;
    const float *w_q, *b_q, *w_k, *b_k, *w_ba, *b_ba, *w_at, *b_at;
    const float *w_p1, *b_p1, *w_p2, *b_p2, *w_p, *b_p;
    const float *w_v1, *b_v1, *w_v2, *b_v2, *w_v, *b_v;
    const int *iidx;
    float *out;
};

__device__ __forceinline__ void fma2(u64 &d, u64 a, u64 b) {
    asm("fma.rn.f32x2 %0, %1, %2, %0;" : "+l"(d) : "l"(a), "l"(b));
}
__device__ __forceinline__ float red2(u64 a) {
    return __uint_as_float((unsigned)a) + __uint_as_float((unsigned)(a >> 32));
}
__device__ __forceinline__ float sigm(float x) { return 1.0f / (1.0f + __expf(-x)); }
__device__ __forceinline__ float tanh_(float x) { return 1.0f - 2.0f / (__expf(2.0f * x) + 1.0f); }
__device__ __forceinline__ float relu_(float x) { return fmaxf(x, 0.0f); }

// 8-col accumulate, single row. Per 4-k step: 1 LDS.128 + 8 LDG.128 + 16 FFMA2.
template <int K>
__device__ __forceinline__ void accum8(u64 acc[8], const float* __restrict__ xr,
                                       const float* __restrict__ w0, int ldw) {
#pragma unroll 2
    for (int k = 0; k < K; k += 4) {
        ulonglong2 x = *(const ulonglong2*)(xr + k);
#pragma unroll
        for (int j = 0; j < 8; j++) {
            ulonglong2 w = __ldg((const ulonglong2*)(w0 + (size_t)j * ldw + k));
            fma2(acc[j], x.x, w.x);
            fma2(acc[j], x.y, w.y);
        }
    }
}

// 16-col accumulate, single row. Per 4-k step: 1 LDS.128 + 16 LDG.128 + 32 FFMA2.
template <int K>
__device__ __forceinline__ void accum16(u64 acc[16], const float* __restrict__ xr,
                                        const float* __restrict__ w0, int ldw) {
#pragma unroll 1
    for (int k = 0; k < K; k += 4) {
        ulonglong2 x = *(const ulonglong2*)(xr + k);
#pragma unroll
        for (int j = 0; j < 16; j++) {
            ulonglong2 w = __ldg((const ulonglong2*)(w0 + (size_t)j * ldw + k));
            fma2(acc[j], x.x, w.x);
            fma2(acc[j], x.y, w.y);
        }
    }
}

extern "C" __global__ void __launch_bounds__(NTHREADS, 1)
actor_kernel(P p) {
    extern __shared__ float sm[];
    float* sx  = sm;                  // 64 x STRIDE activation tiles
    float* swe = sm + M * STRIDE;     // 64 x 28 embedding rows

    const int tid  = threadIdx.x;
    const int lane = tid & 31;
    const int warp = tid >> 5;        // 0..15
    const int half = warp & 1;        // row half
    const int cg   = warp >> 1;       // column group 0..7
    const int myrow = half * 32 + lane;
    const int row0 = blockIdx.x * M;
    const int grow = row0 + myrow;

    // ---- Stage inputs: img->S0, hx_in->S2 ----
    {
        const float4* gi = (const float4*)(p.img + (size_t)row0 * 256);
        const float4* gh = (const float4*)(p.hx0 + (size_t)row0 * 256);
#pragma unroll
        for (int i = tid; i < M * 64; i += NTHREADS) {
            int r = i >> 6, c4 = (i & 63) << 2;
            *(float4*)(sx + r * STRIDE + S0 + c4) = gi[i];
            *(float4*)(sx + r * STRIDE + S2 + c4) = gh[i];
        }
    }
    if (tid < M) {
        int idx = p.iidx[row0 + tid];
        const float* e = p.emb + idx * 25;
#pragma unroll
        for (int k = 0; k < 25; k++) swe[tid * 28 + k] = e[k];
    }
    __syncthreads();

    float* prow = sx + myrow * STRIDE;

    // ---- G0: gated_att = sigmoid(we @ w_ta.T + b_ta) -> S1; gated_fusion -> S0 ----
    {
        const float* xr = swe + myrow * 28;
#pragma unroll 1
        for (int pass = 0; pass < 4; pass++) {
            int cb = pass * 64 + cg * 8;
            float a0[8] = {0,0,0,0,0,0,0,0};
            for (int k = 0; k < 25; k++) {
                float xv = xr[k];
#pragma unroll
                for (int j = 0; j < 8; j++)
                    a0[j] = fmaf(xv, __ldg(p.w_ta + (cb + j) * 25 + k), a0[j]);
            }
#pragma unroll
            for (int j = 0; j < 8; j++) {
                int c = cb + j;
                float ga = sigm(a0[j] + __ldg(p.b_ta + c));
                prow[S1 + c] = ga;
                prow[S0 + c] *= ga;
            }
        }
    }
    __syncthreads();

    // ---- G1: LSTM. warp: 4 logical cols x 4 gates = 16 accs. 8 passes. ----
    {
#pragma unroll 1
        for (int pass = 0; pass < 8; pass++) {
            int c0 = pass * 32 + cg * 4;     // 4-aligned
            u64 acc[16];
#pragma unroll
            for (int j = 0; j < 16; j++) acc[j] = 0;
            const float* wb1 = p.w_ih + (size_t)c0 * 512;
#pragma unroll 1
            for (int k = 0; k < 512; k += 4) {
                ulonglong2 x = *(const ulonglong2*)(prow + k);
#pragma unroll
                for (int j = 0; j < 4; j++)
#pragma unroll
                    for (int g = 0; g < 4; g++) {
                        ulonglong2 w = __ldg((const ulonglong2*)(wb1 + ((size_t)(g << 8) + j) * 512 + k));
                        fma2(acc[j * 4 + g], x.x, w.x);
                        fma2(acc[j * 4 + g], x.y, w.y);
                    }
            }
            const float* wb2 = p.w_hh + (size_t)c0 * 256;
#pragma unroll 1
            for (int k = 0; k < 256; k += 4) {
                ulonglong2 x = *(const ulonglong2*)(prow + S2 + k);
#pragma unroll
                for (int j = 0; j < 4; j++)
#pragma unroll
                    for (int g = 0; g < 4; g++) {
                        ulonglong2 w = __ldg((const ulonglong2*)(wb2 + ((size_t)(g << 8) + j) * 256 + k));
                        fma2(acc[j * 4 + g], x.x, w.x);
                        fma2(acc[j * 4 + g], x.y, w.y);
                    }
            }
            // Epilogue: 4 cols, this thread's row
            float4 bI0 = __ldg((const float4*)(p.b_ih + c0));
            float4 bI1 = __ldg((const float4*)(p.b_hh + c0));
            float4 bF0 = __ldg((const float4*)(p.b_ih + 256 + c0));
            float4 bF1 = __ldg((const float4*)(p.b_hh + 256 + c0));
            float4 bG0 = __ldg((const float4*)(p.b_ih + 512 + c0));
            float4 bG1 = __ldg((const float4*)(p.b_hh + 512 + c0));
            float4 bO0 = __ldg((const float4*)(p.b_ih + 768 + c0));
            float4 bO1 = __ldg((const float4*)(p.b_hh + 768 + c0));
            float bi[4] = {bI0.x + bI1.x, bI0.y + bI1.y, bI0.z + bI1.z, bI0.w + bI1.w};
            float bf[4] = {bF0.x + bF1.x, bF0.y + bF1.y, bF0.z + bF1.z, bF0.w + bF1.w};
            float bg[4] = {bG0.x + bG1.x, bG0.y + bG1.y, bG0.z + bG1.z, bG0.w + bG1.w};
            float bo[4] = {bO0.x + bO1.x, bO0.y + bO1.y, bO0.z + bO1.z, bO0.w + bO1.w};
            float4 cxin = __ldg((const float4*)(p.cx0 + (size_t)grow * 256 + c0));
            float cxa[4] = {cxin.x, cxin.y, cxin.z, cxin.w};
            float cxo[4], hxo[4];
#pragma unroll
            for (int j = 0; j < 4; j++) {
                float iv = sigm (red2(acc[j * 4 + 0]) + bi[j]);
                float fv = sigm (red2(acc[j * 4 + 1]) + bf[j]);
                float gv = tanh_(red2(acc[j * 4 + 2]) + bg[j]);
                float ov = sigm (red2(acc[j * 4 + 3]) + bo[j]);
                float cv = fv * cxa[j] + iv * gv;
                cxo[j] = cv;
                hxo[j] = ov * tanh_(cv);
            }
            *(float4*)(p.out + OFF_CX + (size_t)grow * 256 + c0) = make_float4(cxo[0], cxo[1], cxo[2], cxo[3]);
            *(float4*)(p.out + OFF_HX + (size_t)grow * 256 + c0) = make_float4(hxo[0], hxo[1], hxo[2], hxo[3]);
        }
    }
    __syncthreads();

    // ---- Reload hx from out -> S2 ----
    {
        const float4* gh = (const float4*)(p.out + OFF_HX + (size_t)row0 * 256);
#pragma unroll
        for (int i = tid; i < M * 64; i += NTHREADS) {
            int r = i >> 6, c4 = (i & 63) << 2;
            *(float4*)(sx + r * STRIDE + S2 + c4) = gh[i];
        }
    }
    __syncthreads();

    // ---- G2: mlp_attn = relu([gf(S0)|hx(S2)] @ w_ba.T + b_ba); key->S1, val->scratch ----
    {
#pragma unroll 1
        for (int pass = 0; pass < 4; pass++) {
            int cb = pass * 128 + cg * 16;
            u64 acc[16];
#pragma unroll
            for (int j = 0; j < 16; j++) acc[j] = 0;
            accum16<256>(acc, prow + S0, p.w_ba + (size_t)cb * 512,       512);
            accum16<256>(acc, prow + S2, p.w_ba + (size_t)cb * 512 + 256, 512);
#pragma unroll
            for (int j = 0; j < 16; j++) {
                int c = cb + j;
                float v = relu_(red2(acc[j]) + __ldg(p.b_ba + c));
                if (c < 256) prow[S1 + c] = v;
                else         g_val[(size_t)(c - 256) * B_TOTAL + grow] = v;
            }
        }
    }
    __syncthreads();   // key visible; S0 free

    // ---- Load query -> S0 ----
    {
        const float4* gq = (const float4*)(p.query + (size_t)row0 * 256);
#pragma unroll
        for (int i = tid; i < M * 64; i += NTHREADS) {
            int r = i >> 6, c4 = (i & 63) << 2;
            *(float4*)(sx + r * STRIDE + S0 + c4) = gq[i];
        }
    }
    __syncthreads();

    // ---- G3/G4: q=relu(query@w_q), k=relu(key@w_k); av = tanh(q+k)*val -> scratch ----
    {
#pragma unroll 1
        for (int pass = 0; pass < 4; pass++) {
            int cb = pass * 64 + cg * 8;
            u64 aq[8] = {0,0,0,0,0,0,0,0};
            accum8<256>(aq, prow + S0, p.w_q + (size_t)cb * 256, 256);
            float qv[8];
#pragma unroll
            for (int j = 0; j < 8; j++)
                qv[j] = relu_(red2(aq[j]) + __ldg(p.b_q + cb + j));
            u64 ak[8] = {0,0,0,0,0,0,0,0};
            accum8<256>(ak, prow + S1, p.w_k + (size_t)cb * 256, 256);
#pragma unroll
            for (int j = 0; j < 8; j++) {
                int c = cb + j;
                float ko = relu_(red2(ak[j]) + __ldg(p.b_k + c));
                size_t ib = (size_t)c * B_TOTAL + grow;
                g_val[ib] = tanh_(qv[j] + ko) * g_val[ib];
            }
        }
    }
    __syncthreads();

    // ---- av scratch -> S1 ----
    for (int i = tid; i < M * 256; i += NTHREADS) {
        int c = i >> 6, r = i & 63;
        sx[r * STRIDE + S1 + c] = g_val[(size_t)c * B_TOTAL + row0 + r];
    }
    __syncthreads();

    // ---- G5: attn = relu([av(S1)|hx(S2)] @ w_at.T + b_at) -> S0 (K=512 contiguous) ----
    {
#pragma unroll 1
        for (int pass = 0; pass < 2; pass++) {
            int cb = pass * 128 + cg * 16;
            u64 acc[16];
#pragma unroll
            for (int j = 0; j < 16; j++) acc[j] = 0;
            accum16<512>(acc, prow + S1, p.w_at + (size_t)cb * 512, 512);
#pragma unroll
            for (int j = 0; j < 16; j++) {
                int c = cb + j;
                prow[S0 + c] = relu_(red2(acc[j]) + __ldg(p.b_at + c));
            }
        }
    }
    __syncthreads();

    // ---- G6: pol1(128)->S1[0:128); val1(64)->S1[128:192) ----
    {
#pragma unroll 1
        for (int pass = 0; pass < 2; pass++) {
            int cb = pass * 64 + cg * 8;
            u64 acc[8] = {0,0,0,0,0,0,0,0};
            accum8<256>(acc, prow + S0, p.w_p1 + (size_t)cb * 256, 256);
#pragma unroll
            for (int j = 0; j < 8; j++)
                prow[S1 + cb + j] = relu_(red2(acc[j]) + __ldg(p.b_p1 + cb + j));
        }
        {
            int cb = cg * 8;
            u64 acc[8] = {0,0,0,0,0,0,0,0};
            accum8<256>(acc, prow + S0, p.w_v1 + (size_t)cb * 256, 256);
#pragma unroll
            for (int j = 0; j < 8; j++)
                prow[S1 + 128 + cb + j] = relu_(red2(acc[j]) + __ldg(p.b_v1 + cb + j));
        }
    }
    __syncthreads();

    // ---- G7: pol2(64)->S2[0:64); val2(32)->S2[64:96) ----
    {
        {
            int cb = cg * 8;
            u64 acc[8] = {0,0,0,0,0,0,0,0};
            accum8<128>(acc, prow + S1, p.w_p2 + (size_t)cb * 128, 128);
#pragma unroll
            for (int j = 0; j < 8; j++)
                prow[S2 + cb + j] = relu_(red2(acc[j]) + __ldg(p.b_p2 + cb + j));
        }
        if (cg < 4 && half == 0) {
            int cb = cg * 8;
            u64 acc[8] = {0,0,0,0,0,0,0,0};
            accum8<64>(acc, prow + S1 + 128, p.w_v2 + (size_t)cb * 64, 64);
#pragma unroll
            for (int j = 0; j < 8; j++)
                prow[S2 + 64 + cb + j] = relu_(red2(acc[j]) + __ldg(p.b_v2 + cb + j));
        }
    }
    // val2 for rows 32..63: computed by half==1 warps of cg<4
    if (cg < 4 && half == 1) {
        int cb = cg * 8;
        u64 acc[8] = {0,0,0,0,0,0,0,0};
        accum8<64>(acc, prow + S1 + 128, p.w_v2 + (size_t)cb * 64, 64);
#pragma unroll
        for (int j = 0; j < 8; j++)
            prow[S2 + 64 + cb + j] = relu_(red2(acc[j]) + __ldg(p.b_v2 + cb + j));
    }
    __syncthreads();

    // ---- G8: heads. warps 0,1 -> pol; warps 2,3 -> val ----
    if (warp < 2) {
        int r = lane + (warp & 1) * 32;
        const float* xr = sx + r * STRIDE + S2;
        float a0 = __ldg(p.b_p + 0), a1 = __ldg(p.b_p + 1), a2 = __ldg(p.b_p + 2);
#pragma unroll
        for (int k = 0; k < 64; k++) {
            float x = xr[k];
            a0 = fmaf(x, __ldg(p.w_p + k),       a0);
            a1 = fmaf(x, __ldg(p.w_p + 64 + k),  a1);
            a2 = fmaf(x, __ldg(p.w_p + 128 + k), a2);
        }
        float* po = p.out + OFF_POL + (size_t)(row0 + r) * 3;
        po[0] = a0; po[1] = a1; po[2] = a2;
    } else if (warp < 4) {
        int r = lane + (warp & 1) * 32;
        const float* xr = sx + r * STRIDE + S2 + 64;
        float a = __ldg(p.b_v);
#pragma unroll
        for (int k = 0; k < 32; k++)
            a = fmaf(xr[k], __ldg(p.w_v + k), a);
        p.out[OFF_VAL + row0 + r] = a;
    }
}

extern "C" void kernel_launch(void* const* d_in, const int* in_sizes, int n_in,
                              void* d_out, int out_size) {
    P p;
    p.img   = (const float*)d_in[0];
    p.iidx  = (const int*)  d_in[1];
    p.hx0   = (const float*)d_in[2];
    p.cx0   = (const float*)d_in[3];
    p.query = (const float*)d_in[4];
    p.emb   = (const float*)d_in[5];
    p.w_ta  = (const float*)d_in[6];   p.b_ta = (const float*)d_in[7];
    p.w_ih  = (const float*)d_in[8];   p.w_hh = (const float*)d_in[9];
    p.b_ih  = (const float*)d_in[10];  p.b_hh = (const float*)d_in[11];
    p.w_q   = (const float*)d_in[12];  p.b_q  = (const float*)d_in[13];
    p.w_k   = (const float*)d_in[14];  p.b_k  = (const float*)d_in[15];
    p.w_ba  = (const float*)d_in[16];  p.b_ba = (const float*)d_in[17];
    p.w_at  = (const float*)d_in[18];  p.b_at = (const float*)d_in[19];
    p.w_p1  = (const float*)d_in[20];  p.b_p1 = (const float*)d_in[21];
    p.w_p2  = (const float*)d_in[22];  p.b_p2 = (const float*)d_in[23];
    p.w_p   = (const float*)d_in[24];  p.b_p  = (const float*)d_in[25];
    p.w_v1  = (const float*)d_in[26];  p.b_v1 = (const float*)d_in[27];
    p.w_v2  = (const float*)d_in[28];  p.b_v2 = (const float*)d_in[29];
    p.w_v   = (const float*)d_in[30];  p.b_v  = (const float*)d_in[31];
    p.out   = (float*)d_out;

    size_t smem = (size_t)(M * STRIDE + M * 28) * sizeof(float);  // 204,800 B
    cudaFuncSetAttribute(actor_kernel, cudaFuncAttributeMaxDynamicSharedMemorySize, (int)smem);
    actor_kernel<<<B_TOTAL / M, NTHREADS, smem>>>(p);
}

// round 9
// speedup vs baseline: 1.6326x; 1.6326x over previous
#include <cuda_runtime.h>

// Actor_Critic fused — Round 8: fp32 FFMA2, M=64 rows/block, 512 threads / 16 warps.
// Each thread owns 2 rows (lane, lane+32); all 16 warps cover all rows and
// partition 16 column-groups of 8. Same L1 traffic as R5, 2x warps/SMSP.

#define B_TOTAL 32768
#define M 64
#define STRIDE 772           // 3*256+4 floats
#define NTHREADS 512
#define S0 0
#define S1 256
#define S2 512

#define OFF_VAL 0
#define OFF_POL (B_TOTAL)
#define OFF_HX  (B_TOTAL * 4)
#define OFF_CX  (B_TOTAL * 4 + B_TOTAL * 256)

typedef unsigned long long u64;

// column-major scratch: g_val[c * B_TOTAL + row]
__device__ float g_val[(size_t)256 * B_TOTAL];

struct P {
    const float *img, *hx0, *cx0, *query, *emb;
    const float *w_ta, *b_ta, *w_ih, *w_hh, *b_ih, *b_hh;
    const float *w_q, *b_q, *w_k, *b_k, *w_ba, *b_ba, *w_at, *b_at;
    const float *w_p1, *b_p1, *w_p2, *b_p2, *w_p, *b_p;
    const float *w_v1, *b_v1, *w_v2, *b_v2, *w_v, *b_v;
    const int *iidx;
    float *out;
};

__device__ __forceinline__ void fma2(u64 &d, u64 a, u64 b) {
    asm("fma.rn.f32x2 %0, %1, %2, %0;" : "+l"(d) : "l"(a), "l"(b));
}
__device__ __forceinline__ float red2(u64 a) {
    return __uint_as_float((unsigned)a) + __uint_as_float((unsigned)(a >> 32));
}
__device__ __forceinline__ float sigm(float x) { return 1.0f / (1.0f + __expf(-x)); }
__device__ __forceinline__ float tanh_(float x) { return 1.0f - 2.0f / (__expf(2.0f * x) + 1.0f); }
__device__ __forceinline__ float relu_(float x) { return fmaxf(x, 0.0f); }

// 8 cols x 2 rows. Per 4-k step: 2 LDS.128 + 8 LDG.128 + 32 FFMA2 (2048 MACs/warp).
template <int K>
__device__ __forceinline__ void accum8x2(u64 aA[8], u64 aB[8],
                                         const float* __restrict__ xa,
                                         const float* __restrict__ xb,
                                         const float* __restrict__ w0, int ldw) {
#pragma unroll 2
    for (int k = 0; k < K; k += 4) {
        ulonglong2 x0 = *(const ulonglong2*)(xa + k);
        ulonglong2 x1 = *(const ulonglong2*)(xb + k);
#pragma unroll
        for (int j = 0; j < 8; j++) {
            ulonglong2 w = __ldg((const ulonglong2*)(w0 + (size_t)j * ldw + k));
            fma2(aA[j], x0.x, w.x); fma2(aA[j], x0.y, w.y);
            fma2(aB[j], x1.x, w.x); fma2(aB[j], x1.y, w.y);
        }
    }
}

extern "C" __global__ void __launch_bounds__(NTHREADS, 1)
actor_kernel(P p) {
    extern __shared__ float sm[];
    float* sx  = sm;                  // 64 x STRIDE activation tiles
    float* swe = sm + M * STRIDE;     // 64 x 28 embedding rows

    const int tid  = threadIdx.x;
    const int lane = tid & 31;
    const int cg   = tid >> 5;        // column group 0..15
    const int row0 = blockIdx.x * M;

    // ---- Stage inputs: img->S0, hx_in->S2 ----
    {
        const float4* gi = (const float4*)(p.img + (size_t)row0 * 256);
        const float4* gh = (const float4*)(p.hx0 + (size_t)row0 * 256);
#pragma unroll
        for (int i = tid; i < M * 64; i += NTHREADS) {
            int r = i >> 6, c4 = (i & 63) << 2;
            *(float4*)(sx + r * STRIDE + S0 + c4) = gi[i];
            *(float4*)(sx + r * STRIDE + S2 + c4) = gh[i];
        }
    }
    if (tid < M) {
        int idx = p.iidx[row0 + tid];
        const float* e = p.emb + idx * 25;
#pragma unroll
        for (int k = 0; k < 25; k++) swe[tid * 28 + k] = e[k];
    }
    __syncthreads();

    float* prow_a = sx + lane * STRIDE;
    float* prow_b = prow_a + 32 * STRIDE;

    // ---- G0: gated_att = sigmoid(we @ w_ta.T + b_ta) -> S1; gated_fusion -> S0 ----
    {
#pragma unroll 1
        for (int pass = 0; pass < 2; pass++) {
            int cb = pass * 128 + cg * 8;
            float a0[8] = {0,0,0,0,0,0,0,0}, a1[8] = {0,0,0,0,0,0,0,0};
            for (int k = 0; k < 25; k++) {
                float xa = swe[lane * 28 + k], xb = swe[(lane + 32) * 28 + k];
#pragma unroll
                for (int j = 0; j < 8; j++) {
                    float w = __ldg(p.w_ta + (cb + j) * 25 + k);
                    a0[j] = fmaf(xa, w, a0[j]);
                    a1[j] = fmaf(xb, w, a1[j]);
                }
            }
#pragma unroll
            for (int j = 0; j < 8; j++) {
                int c = cb + j;
                float b = __ldg(p.b_ta + c);
                float gA = sigm(a0[j] + b), gB = sigm(a1[j] + b);
                prow_a[S1 + c] = gA;  prow_a[S0 + c] *= gA;
                prow_b[S1 + c] = gB;  prow_b[S0 + c] *= gB;
            }
        }
    }
    __syncthreads();

    // ---- G1: LSTM. 8 passes; warp: 2 logical cols x 4 gates x 2 rows = 16 accs ----
    {
#pragma unroll 1
        for (int pass = 0; pass < 8; pass++) {
            int c0 = pass * 32 + cg * 2;       // even -> float2-aligned col pair
            u64 aA[8] = {0,0,0,0,0,0,0,0};     // [j*4+g] rows lane
            u64 aB[8] = {0,0,0,0,0,0,0,0};     // rows lane+32
#pragma unroll 2
            for (int k = 0; k < 512; k += 4) {
                ulonglong2 x0 = *(const ulonglong2*)(prow_a + k);
                ulonglong2 x1 = *(const ulonglong2*)(prow_b + k);
#pragma unroll
                for (int j = 0; j < 2; j++)
#pragma unroll
                    for (int g = 0; g < 4; g++) {
                        ulonglong2 w = __ldg((const ulonglong2*)(p.w_ih + (size_t)((g << 8) + c0 + j) * 512 + k));
                        fma2(aA[j*4+g], x0.x, w.x); fma2(aA[j*4+g], x0.y, w.y);
                        fma2(aB[j*4+g], x1.x, w.x); fma2(aB[j*4+g], x1.y, w.y);
                    }
            }
#pragma unroll 2
            for (int k = 0; k < 256; k += 4) {
                ulonglong2 x0 = *(const ulonglong2*)(prow_a + S2 + k);
                ulonglong2 x1 = *(const ulonglong2*)(prow_b + S2 + k);
#pragma unroll
                for (int j = 0; j < 2; j++)
#pragma unroll
                    for (int g = 0; g < 4; g++) {
                        ulonglong2 w = __ldg((const ulonglong2*)(p.w_hh + (size_t)((g << 8) + c0 + j) * 256 + k));
                        fma2(aA[j*4+g], x0.x, w.x); fma2(aA[j*4+g], x0.y, w.y);
                        fma2(aB[j*4+g], x1.x, w.x); fma2(aB[j*4+g], x1.y, w.y);
                    }
            }
            // Epilogue: cell update; hx/cx -> out (float2 col-pair stores)
            float bI0 = __ldg(p.b_ih + c0)           + __ldg(p.b_hh + c0);
            float bI1 = __ldg(p.b_ih + c0 + 1)       + __ldg(p.b_hh + c0 + 1);
            float bF0 = __ldg(p.b_ih + 256 + c0)     + __ldg(p.b_hh + 256 + c0);
            float bF1 = __ldg(p.b_ih + 256 + c0 + 1) + __ldg(p.b_hh + 256 + c0 + 1);
            float bG0 = __ldg(p.b_ih + 512 + c0)     + __ldg(p.b_hh + 512 + c0);
            float bG1 = __ldg(p.b_ih + 512 + c0 + 1) + __ldg(p.b_hh + 512 + c0 + 1);
            float bO0 = __ldg(p.b_ih + 768 + c0)     + __ldg(p.b_hh + 768 + c0);
            float bO1 = __ldg(p.b_ih + 768 + c0 + 1) + __ldg(p.b_hh + 768 + c0 + 1);
#pragma unroll
            for (int r = 0; r < 2; r++) {
                int row = row0 + lane + r * 32;
                float2 cxin = __ldg((const float2*)(p.cx0 + (size_t)row * 256 + c0));
                float i0 = sigm ((r ? red2(aB[0]) : red2(aA[0])) + bI0);
                float f0 = sigm ((r ? red2(aB[1]) : red2(aA[1])) + bF0);
                float g0 = tanh_((r ? red2(aB[2]) : red2(aA[2])) + bG0);
                float o0 = sigm ((r ? red2(aB[3]) : red2(aA[3])) + bO0);
                float i1 = sigm ((r ? red2(aB[4]) : red2(aA[4])) + bI1);
                float f1 = sigm ((r ? red2(aB[5]) : red2(aA[5])) + bF1);
                float g1 = tanh_((r ? red2(aB[6]) : red2(aA[6])) + bG1);
                float o1 = sigm ((r ? red2(aB[7]) : red2(aA[7])) + bO1);
                float2 cxo, hxo;
                cxo.x = f0 * cxin.x + i0 * g0;  hxo.x = o0 * tanh_(cxo.x);
                cxo.y = f1 * cxin.y + i1 * g1;  hxo.y = o1 * tanh_(cxo.y);
                *(float2*)(p.out + OFF_CX + (size_t)row * 256 + c0) = cxo;
                *(float2*)(p.out + OFF_HX + (size_t)row * 256 + c0) = hxo;
            }
        }
    }
    __syncthreads();

    // ---- Reload hx from out -> S2 ----
    {
        const float4* gh = (const float4*)(p.out + OFF_HX + (size_t)row0 * 256);
#pragma unroll
        for (int i = tid; i < M * 64; i += NTHREADS) {
            int r = i >> 6, c4 = (i & 63) << 2;
            *(float4*)(sx + r * STRIDE + S2 + c4) = gh[i];
        }
    }
    __syncthreads();

    // ---- G2: mlp_attn = relu([gf(S0)|hx(S2)] @ w_ba.T + b_ba); key->S1, val->scratch ----
    {
#pragma unroll 1
        for (int pass = 0; pass < 4; pass++) {
            int cb = pass * 128 + cg * 8;
            u64 aA[8] = {0,0,0,0,0,0,0,0}, aB[8] = {0,0,0,0,0,0,0,0};
            accum8x2<256>(aA, aB, prow_a + S0, prow_b + S0, p.w_ba + (size_t)cb * 512,       512);
            accum8x2<256>(aA, aB, prow_a + S2, prow_b + S2, p.w_ba + (size_t)cb * 512 + 256, 512);
#pragma unroll
            for (int j = 0; j < 8; j++) {
                int c = cb + j;
                float b = __ldg(p.b_ba + c);
                float vA = relu_(red2(aA[j]) + b), vB = relu_(red2(aB[j]) + b);
                if (c < 256) { prow_a[S1 + c] = vA; prow_b[S1 + c] = vB; }
                else {
                    size_t ib = (size_t)(c - 256) * B_TOTAL + row0 + lane;
                    g_val[ib] = vA; g_val[ib + 32] = vB;
                }
            }
        }
    }
    __syncthreads();   // key visible; S0 free

    // ---- Load query -> S0 ----
    {
        const float4* gq = (const float4*)(p.query + (size_t)row0 * 256);
#pragma unroll
        for (int i = tid; i < M * 64; i += NTHREADS) {
            int r = i >> 6, c4 = (i & 63) << 2;
            *(float4*)(sx + r * STRIDE + S0 + c4) = gq[i];
        }
    }
    __syncthreads();

    // ---- G3/G4: q=relu(query@w_q), k=relu(key@w_k); av = tanh(q+k)*val -> scratch ----
    {
#pragma unroll 1
        for (int pass = 0; pass < 2; pass++) {
            int cb = pass * 128 + cg * 8;
            u64 aA[8] = {0,0,0,0,0,0,0,0}, aB[8] = {0,0,0,0,0,0,0,0};
            accum8x2<256>(aA, aB, prow_a + S0, prow_b + S0, p.w_q + (size_t)cb * 256, 256);
            float qA[8], qB[8];
#pragma unroll
            for (int j = 0; j < 8; j++) {
                float b = __ldg(p.b_q + cb + j);
                qA[j] = relu_(red2(aA[j]) + b);
                qB[j] = relu_(red2(aB[j]) + b);
            }
            u64 kA[8] = {0,0,0,0,0,0,0,0}, kB[8] = {0,0,0,0,0,0,0,0};
            accum8x2<256>(kA, kB, prow_a + S1, prow_b + S1, p.w_k + (size_t)cb * 256, 256);
#pragma unroll
            for (int j = 0; j < 8; j++) {
                int c = cb + j;
                float b = __ldg(p.b_k + c);
                float koA = relu_(red2(kA[j]) + b), koB = relu_(red2(kB[j]) + b);
                size_t ib = (size_t)c * B_TOTAL + row0 + lane;
                float avA = tanh_(qA[j] + koA) * g_val[ib];
                float avB = tanh_(qB[j] + koB) * g_val[ib + 32];
                g_val[ib] = avA; g_val[ib + 32] = avB;
            }
        }
    }
    __syncthreads();

    // ---- av scratch -> S1 ----
    for (int i = tid; i < M * 256; i += NTHREADS) {
        int c = i >> 6, r = i & 63;
        sx[r * STRIDE + S1 + c] = g_val[(size_t)c * B_TOTAL + row0 + r];
    }
    __syncthreads();

    // ---- G5: attn = relu([av(S1)|hx(S2)] @ w_at.T + b_at) -> S0 (K=512 contiguous) ----
    {
#pragma unroll 1
        for (int pass = 0; pass < 2; pass++) {
            int cb = pass * 128 + cg * 8;
            u64 aA[8] = {0,0,0,0,0,0,0,0}, aB[8] = {0,0,0,0,0,0,0,0};
            accum8x2<512>(aA, aB, prow_a + S1, prow_b + S1, p.w_at + (size_t)cb * 512, 512);
#pragma unroll
            for (int j = 0; j < 8; j++) {
                int c = cb + j;
                float b = __ldg(p.b_at + c);
                prow_a[S0 + c] = relu_(red2(aA[j]) + b);
                prow_b[S0 + c] = relu_(red2(aB[j]) + b);
            }
        }
    }
    __syncthreads();

    // ---- G6: pol1(128) -> S1[0:128) by cg 0-15; val1(64) -> S1[128:192) by cg 0-7 ----
    {
        {
            int cb = cg * 8;
            u64 aA[8] = {0,0,0,0,0,0,0,0}, aB[8] = {0,0,0,0,0,0,0,0};
            accum8x2<256>(aA, aB, prow_a + S0, prow_b + S0, p.w_p1 + (size_t)cb * 256, 256);
#pragma unroll
            for (int j = 0; j < 8; j++) {
                float b = __ldg(p.b_p1 + cb + j);
                prow_a[S1 + cb + j] = relu_(red2(aA[j]) + b);
                prow_b[S1 + cb + j] = relu_(red2(aB[j]) + b);
            }
        }
        if (cg < 8) {
            int cb = cg * 8;
            u64 aA[8] = {0,0,0,0,0,0,0,0}, aB[8] = {0,0,0,0,0,0,0,0};
            accum8x2<256>(aA, aB, prow_a + S0, prow_b + S0, p.w_v1 + (size_t)cb * 256, 256);
#pragma unroll
            for (int j = 0; j < 8; j++) {
                float b = __ldg(p.b_v1 + cb + j);
                prow_a[S1 + 128 + cb + j] = relu_(red2(aA[j]) + b);
                prow_b[S1 + 128 + cb + j] = relu_(red2(aB[j]) + b);
            }
        }
    }
    __syncthreads();

    // ---- G7: pol2(64) -> S2[0:64) by cg 0-7; val2(32) -> S2[64:96) by cg 8-11 ----
    {
        if (cg < 8) {
            int cb = cg * 8;
            u64 aA[8] = {0,0,0,0,0,0,0,0}, aB[8] = {0,0,0,0,0,0,0,0};
            accum8x2<128>(aA, aB, prow_a + S1, prow_b + S1, p.w_p2 + (size_t)cb * 128, 128);
#pragma unroll
            for (int j = 0; j < 8; j++) {
                float b = __ldg(p.b_p2 + cb + j);
                prow_a[S2 + cb + j] = relu_(red2(aA[j]) + b);
                prow_b[S2 + cb + j] = relu_(red2(aB[j]) + b);
            }
        } else if (cg < 12) {
            int cb = (cg - 8) * 8;
            u64 aA[8] = {0,0,0,0,0,0,0,0}, aB[8] = {0,0,0,0,0,0,0,0};
            accum8x2<64>(aA, aB, prow_a + S1 + 128, prow_b + S1 + 128, p.w_v2 + (size_t)cb * 64, 64);
#pragma unroll
            for (int j = 0; j < 8; j++) {
                float b = __ldg(p.b_v2 + cb + j);
                prow_a[S2 + 64 + cb + j] = relu_(red2(aA[j]) + b);
                prow_b[S2 + 64 + cb + j] = relu_(red2(aB[j]) + b);
            }
        }
    }
    __syncthreads();

    // ---- G8: heads. warps 0,1 -> pol rows; warps 2,3 -> val rows ----
    if (cg < 2) {
        int r = lane + (cg & 1) * 32;
        const float* xr = sx + r * STRIDE + S2;
        float a0 = __ldg(p.b_p + 0), a1 = __ldg(p.b_p + 1), a2 = __ldg(p.b_p + 2);
#pragma unroll
        for (int k = 0; k < 64; k++) {
            float x = xr[k];
            a0 = fmaf(x, __ldg(p.w_p + k),       a0);
            a1 = fmaf(x, __ldg(p.w_p + 64 + k),  a1);
            a2 = fmaf(x, __ldg(p.w_p + 128 + k), a2);
        }
        float* po = p.out + OFF_POL + (size_t)(row0 + r) * 3;
        po[0] = a0; po[1] = a1; po[2] = a2;
    } else if (cg < 4) {
        int r = lane + (cg & 1) * 32;
        const float* xr = sx + r * STRIDE + S2 + 64;
        float a = __ldg(p.b_v);
#pragma unroll
        for (int k = 0; k < 32; k++)
            a = fmaf(xr[k], __ldg(p.w_v + k), a);
        p.out[OFF_VAL + row0 + r] = a;
    }
}

extern "C" void kernel_launch(void* const* d_in, const int* in_sizes, int n_in,
                              void* d_out, int out_size) {
    P p;
    p.img   = (const float*)d_in[0];
    p.iidx  = (const int*)  d_in[1];
    p.hx0   = (const float*)d_in[2];
    p.cx0   = (const float*)d_in[3];
    p.query = (const float*)d_in[4];
    p.emb   = (const float*)d_in[5];
    p.w_ta  = (const float*)d_in[6];   p.b_ta = (const float*)d_in[7];
    p.w_ih  = (const float*)d_in[8];   p.w_hh = (const float*)d_in[9];
    p.b_ih  = (const float*)d_in[10];  p.b_hh = (const float*)d_in[11];
    p.w_q   = (const float*)d_in[12];  p.b_q  = (const float*)d_in[13];
    p.w_k   = (const float*)d_in[14];  p.b_k  = (const float*)d_in[15];
    p.w_ba  = (const float*)d_in[16];  p.b_ba = (const float*)d_in[17];
    p.w_at  = (const float*)d_in[18];  p.b_at = (const float*)d_in[19];
    p.w_p1  = (const float*)d_in[20];  p.b_p1 = (const float*)d_in[21];
    p.w_p2  = (const float*)d_in[22];  p.b_p2 = (const float*)d_in[23];
    p.w_p   = (const float*)d_in[24];  p.b_p  = (const float*)d_in[25];
    p.w_v1  = (const float*)d_in[26];  p.b_v1 = (const float*)d_in[27];
    p.w_v2  = (const float*)d_in[28];  p.b_v2 = (const float*)d_in[29];
    p.w_v   = (const float*)d_in[30];  p.b_v  = (const float*)d_in[31];
    p.out   = (float*)d_out;

    size_t smem = (size_t)(M * STRIDE + M * 28) * sizeof(float);  // 204,800 B
    cudaFuncSetAttribute(actor_kernel, cudaFuncAttributeMaxDynamicSharedMemorySize, (int)smem);
    actor_kernel<<<B_TOTAL / M, NTHREADS, smem>>>(p);
}